// round 15
// baseline (speedup 1.0000x reference)
#include <cuda_runtime.h>
#include <math.h>

#define BB 16
#define GG 1600
#define DD 2048
#define MM 64
#define WG 40
#define NS 4               // box slices
#define BPS (MM / NS)      // 16 boxes per slice
#define NBLK (BB * GG / 8) // 3200 blocks, warp-per-row
#define BPB 200            // blocks per batch (3200/16)

// ---- device-global scratch (no allocations allowed) ----
__device__ float g_var[BB * GG];
__device__ unsigned long long g_pmask[NS][BB * GG];  // partial inside|argmin masks
__device__ float g_loss_b[BB];
__device__ int   g_pos_b[BB];
__device__ unsigned int g_tick[BB];   // per-batch tickets (modular, no reset needed)
__device__ unsigned int g_tick2;      // final ticket

// Single fused kernel.
//  * warp-per-row variance (MLP=16, __ldcs, no barrier in the var path)
//  * mask slices on the first 28 blocks OF EACH BATCH GROUP (so batch b's
//    masks and vars all come from blocks [200b, 200b+200))
//  * per-batch threadFenceReduction ticket: the 200th finisher of a batch
//    gathers its 1600 cells (L2-hot) into SHARED accumulators, computes the
//    batch's loss partial, and the 16th batch-finisher writes the output.
//  Only 3200 t0 fences total (R6 measured the poison at 25600 fences; 22/SM
//  here costs ~2us). Tickets compare modulo, so no zero-init anywhere.
__global__ void __launch_bounds__(256) fused_kernel(const float* __restrict__ atten,
                                                    const float* __restrict__ bboxes,
                                                    float* __restrict__ out) {
    const int t = threadIdx.x;
    const int batch = blockIdx.x / BPB;
    const int local = blockIdx.x % BPB;

    // ---- variance: one warp per (b,g) row ----
    const int row  = blockIdx.x * 8 + (t >> 5);
    const int lane = t & 31;
    const float4* p = reinterpret_cast<const float4*>(atten) + (size_t)row * (DD / 4);

    // shift by 0.5 (inputs U[0,1]) to kill cancellation in sumsq - sum^2/n;
    // two accumulator pairs to halve the serial FADD/FFMA chains.
    float sa = 0.0f, sb = 0.0f, qa = 0.0f, qb = 0.0f;
#pragma unroll
    for (int j = 0; j < 16; j++) {
        float4 v = __ldcs(p + lane + 32 * j);
        float a0 = v.x - 0.5f, a1 = v.y - 0.5f, a2 = v.z - 0.5f, a3 = v.w - 0.5f;
        sa += a0; sb += a1; sa += a2; sb += a3;
        qa = fmaf(a0, a0, qa); qb = fmaf(a1, a1, qb);
        qa = fmaf(a2, a2, qa); qb = fmaf(a3, a3, qb);
    }
    float s = sa + sb, s2 = qa + qb;
#pragma unroll
    for (int o = 16; o > 0; o >>= 1) {
        s  += __shfl_xor_sync(0xFFFFFFFFu, s,  o);
        s2 += __shfl_xor_sync(0xFFFFFFFFu, s2, o);
    }
    if (lane == 0)
        g_var[row] = (s2 - s * s / (float)DD) / (float)(DD - 1);

    // ---- mask slice on the first 28 blocks of each batch group ----
    if (local < 28) {
        const int slice = local & 3;
        const int chunk = local >> 2;
        const int b = batch;

        __shared__ float s_corx[BPS][4], s_cory[BPS][4];
        __shared__ int   s_gmin[BPS];

        if (t < BPS) {
            const int box = slice * BPS + t;
            const float* bbp = bboxes + ((size_t)b * MM + box) * 7;
            float cx = bbp[0], cy = bbp[1];
            float l = bbp[3], w = bbp[4];
            float ang = bbp[6];
            float rl = fminf(fmaxf(2.56f / l, 1.0f), 6.0f);
            float rw = fminf(fmaxf(2.56f / w, 1.0f), 6.0f);
            float el = l * rl, ew = w * rw;
            float c = cosf(ang), sn = sinf(ang);
            const float cnx[4] = {-0.5f, -0.5f, 0.5f, 0.5f};
            const float cny[4] = {-0.5f,  0.5f, 0.5f, -0.5f};
#pragma unroll
            for (int k = 0; k < 4; k++) {
                float lx = cnx[k] * el, ly = cny[k] * ew;
                s_corx[t][k] = c * lx - sn * ly + cx;
                s_cory[t][k] = sn * lx + c * ly + cy;
            }

            // analytic argmin: 4x4 clamped window around the center contains
            // all fp-rounded tie candidates; lexicographic (d, idx) min with
            // reference-exact rn arithmetic == jnp.argmin first-occurrence.
            float wf = (cx + 51.2f) / 2.56f - 0.5f;
            float hf = (cy + 51.2f) / 2.56f - 0.5f;
            int w0 = min(max((int)floorf(wf) - 1, 0), WG - 4);
            int h0 = min(max((int)floorf(hf) - 1, 0), WG - 4);
            float bd = 3.0e38f;
            int   bg = 1 << 30;
#pragma unroll
            for (int dh = 0; dh < 4; dh++) {
#pragma unroll
                for (int dw = 0; dw < 4; dw++) {
                    int hi = h0 + dh, wi = w0 + dw;
                    float px = ((float)wi + 0.5f) / 40.0f * 102.4f - 51.2f;
                    float py = ((float)hi + 0.5f) / 40.0f * 102.4f - 51.2f;
                    float dx = __fsub_rn(px, cx), dy = __fsub_rn(py, cy);
                    float d = __fadd_rn(__fmul_rn(dx, dx), __fmul_rn(dy, dy));
                    if (d < bd) { bd = d; bg = hi * WG + wi; }
                }
            }
            s_gmin[t] = bg;
        }
        __syncthreads();

        const int cell = chunk * 256 + t;
        if (cell < GG) {
            const int wi = cell % WG, hi = cell / WG;
            const float px = ((float)wi + 0.5f) / 40.0f * 102.4f - 51.2f;
            const float py = ((float)hi + 0.5f) / 40.0f * 102.4f - 51.2f;

            unsigned long long m = 0ull;
#pragma unroll 4
            for (int i = 0; i < BPS; i++) {
                const float x0 = s_corx[i][0], y0 = s_cory[i][0];
                const float x1 = s_corx[i][1], y1 = s_cory[i][1];
                const float x2 = s_corx[i][2], y2 = s_cory[i][2];
                const float x3 = s_corx[i][3], y3 = s_cory[i][3];
                const float e0x = x1 - x0, e0y = y1 - y0;
                const float e1x = x2 - x1, e1y = y2 - y1;
                const float e2x = x3 - x2, e2y = y3 - y2;
                const float e3x = x0 - x3, e3y = y0 - y3;
                float c0 = e0x * (py - y0) - e0y * (px - x0);
                float c1 = e1x * (py - y1) - e1y * (px - x1);
                float c2 = e2x * (py - y2) - e2y * (px - x2);
                float c3 = e3x * (py - y3) - e3y * (px - x3);
                bool allpos = (c0 >= 0.0f) & (c1 >= 0.0f) & (c2 >= 0.0f) & (c3 >= 0.0f);
                bool allneg = (c0 <= 0.0f) & (c1 <= 0.0f) & (c2 <= 0.0f) & (c3 <= 0.0f);
                bool ins = (allpos | allneg) | (s_gmin[i] == cell);
                if (ins) m |= (1ull << (slice * BPS + i));
            }
            g_pmask[slice][b * GG + cell] = m;
        }
    }

    // ---- per-batch ticket (release: stores -> syncthreads -> t0 fence+add) ----
    __syncthreads();
    __shared__ unsigned int s_old;
    if (t == 0) {
        __threadfence();                       // cumulative release for all CTA stores
        s_old = atomicAdd(&g_tick[batch], 1u);
    }
    __syncthreads();
    if ((s_old + 1u) % (unsigned)BPB != 0u) return;

    // ---- this block is the 200th finisher of `batch`: gather it ----
    __shared__ float s_sums[MM];
    __shared__ int   s_cnt[MM];
    if (t == 0) __threadfence();               // cumulative acquire
    if (t < MM) { s_sums[t] = 0.0f; s_cnt[t] = 0; }
    __syncthreads();                           // propagates t0's acquire to all

    const int base = batch * GG;
#pragma unroll
    for (int k = 0; k < 7; k++) {
        int cell = t + k * 256;
        if (cell < GG) {
            int r = base + cell;
            unsigned long long m = __ldcg(&g_pmask[0][r]) | __ldcg(&g_pmask[1][r])
                                 | __ldcg(&g_pmask[2][r]) | __ldcg(&g_pmask[3][r]);
            // flag = parity(mask)? msb(mask) : -1 (the reference scan's
            // all_free coupling is dead: each covering box toggles the cell)
            if (__popcll(m) & 1) {
                int f = 63 - __clzll(m);
                atomicAdd(&s_sums[f], __ldcg(&g_var[r]));
                atomicAdd(&s_cnt[f], 1);
            }
        }
    }
    __syncthreads();

    // per-box means -> batch partial (warps 0-1 hold boxes 0..63)
    float term = 0.0f;
    int   pos  = 0;
    if (t < MM) {
        int c = s_cnt[t];
        if (c > 0) { term = s_sums[t] / (float)c; pos = 1; }
    }
#pragma unroll
    for (int o = 16; o > 0; o >>= 1) {
        term += __shfl_xor_sync(0xFFFFFFFFu, term, o);
        pos  += __shfl_xor_sync(0xFFFFFFFFu, pos,  o);
    }
    __shared__ float s_l[2];
    __shared__ int   s_p[2];
    if (t == 0)  { s_l[0] = term; s_p[0] = pos; }
    if (t == 32) { s_l[1] = term; s_p[1] = pos; }
    __syncthreads();

    if (t == 0) {
        g_loss_b[batch] = s_l[0] + s_l[1];
        g_pos_b[batch]  = s_p[0] + s_p[1];
        __threadfence();                       // release batch partial
        unsigned int o2 = atomicAdd(&g_tick2, 1u);
        if ((o2 + 1u) % (unsigned)BB == 0u) {  // 16th batch finisher finalizes
            __threadfence();                   // acquire
            float L = 0.0f;
            int   P = 0;
#pragma unroll
            for (int i = 0; i < BB; i++) {
                L += __ldcg(&g_loss_b[i]);
                P += __ldcg(&g_pos_b[i]);
            }
            if (P < 1) P = 1;
            out[0] = -L / (float)P;
        }
    }
}

extern "C" void kernel_launch(void* const* d_in, const int* in_sizes, int n_in,
                              void* d_out, int out_size) {
    const float* atten = (const float*)d_in[0];   // (16, 1600, 2048) fp32
    const float* bbox  = (const float*)d_in[1];   // (16, 64, 7) fp32
    float* out = (float*)d_out;

    fused_kernel<<<NBLK, 256>>>(atten, bbox, out);
}

// round 16
// speedup vs baseline: 1.0991x; 1.0991x over previous
#include <cuda_runtime.h>
#include <math.h>

#define BB 16
#define GG 1600
#define DD 2048
#define MM 64
#define WG 40
#define NS 4              // box slices
#define BPS (MM / NS)     // 16 boxes per slice
#define NMASKBLK (BB * 7 * NS)   // 448 mask-carrying blocks
#define NGATHER (BB * 7)         // 112 gather blocks
#define NBLK_VAR (BB * GG / 8)   // 3200 blocks, warp-per-row

// ---- device-global scratch (no allocations allowed) ----
__device__ float g_var[BB * GG];
__device__ unsigned long long g_pmask[NS][BB * GG];  // partial inside|argmin masks
__device__ float g_sums[BB * MM];
__device__ int   g_cnt[BB * MM];
__device__ int   g_done;

// Fused kernel: WARP-per-row variance (MLP=16, no block barrier, no fences/
// atomics anywhere in the streaming path — the settled result of R4-R15 is
// that ANY sync machinery in this kernel costs ~10-12us) + mask slices on
// blocks 0..447 + accumulator zero-init on blocks 0..7.
__global__ void __launch_bounds__(256) var_mask_kernel(const float* __restrict__ atten,
                                                       const float* __restrict__ bboxes) {
    const int t = threadIdx.x;
    if (blockIdx.x < 8) {
        int gid = blockIdx.x * 256 + t;          // 2048 slots = 1024 + 1024
        if (gid < BB * MM) g_sums[gid] = 0.0f;
        else g_cnt[gid - BB * MM] = 0;
        if (gid == 0) g_done = 0;
    }

    // ---- variance: one warp per (b,g) row ----
    const int row  = blockIdx.x * 8 + (t >> 5);
    const int lane = t & 31;
    const float4* p = reinterpret_cast<const float4*>(atten) + (size_t)row * (DD / 4);

    // shift by 0.5 (inputs U[0,1]) to kill cancellation in sumsq - sum^2/n;
    // two accumulator pairs to halve the serial FADD/FFMA chains.
    float sa = 0.0f, sb = 0.0f, qa = 0.0f, qb = 0.0f;
#pragma unroll
    for (int j = 0; j < 16; j++) {
        float4 v = __ldcs(p + lane + 32 * j);
        float a0 = v.x - 0.5f, a1 = v.y - 0.5f, a2 = v.z - 0.5f, a3 = v.w - 0.5f;
        sa += a0; sb += a1; sa += a2; sb += a3;
        qa = fmaf(a0, a0, qa); qb = fmaf(a1, a1, qb);
        qa = fmaf(a2, a2, qa); qb = fmaf(a3, a3, qb);
    }
    float s = sa + sb, s2 = qa + qb;
#pragma unroll
    for (int o = 16; o > 0; o >>= 1) {
        s  += __shfl_xor_sync(0xFFFFFFFFu, s,  o);
        s2 += __shfl_xor_sync(0xFFFFFFFFu, s2, o);
    }
    if (lane == 0)
        g_var[row] = (s2 - s * s / (float)DD) / (float)(DD - 1);

    // ---- mask slice on the first 448 blocks ----
    if (blockIdx.x < NMASKBLK) {
        const int slice = blockIdx.x & (NS - 1);
        const int bc    = blockIdx.x >> 2;       // b*7 + chunk
        const int b     = bc / 7;
        const int chunk = bc % 7;

        __shared__ float s_corx[BPS][4], s_cory[BPS][4];
        __shared__ int   s_gmin[BPS];

        if (t < BPS) {
            const int box = slice * BPS + t;
            const float* bbp = bboxes + ((size_t)b * MM + box) * 7;
            float cx = bbp[0], cy = bbp[1];
            float l = bbp[3], w = bbp[4];
            float ang = bbp[6];
            float rl = fminf(fmaxf(2.56f / l, 1.0f), 6.0f);
            float rw = fminf(fmaxf(2.56f / w, 1.0f), 6.0f);
            float el = l * rl, ew = w * rw;
            float c = cosf(ang), sn = sinf(ang);
            const float cnx[4] = {-0.5f, -0.5f, 0.5f, 0.5f};
            const float cny[4] = {-0.5f,  0.5f, 0.5f, -0.5f};
#pragma unroll
            for (int k = 0; k < 4; k++) {
                float lx = cnx[k] * el, ly = cny[k] * ew;
                s_corx[t][k] = c * lx - sn * ly + cx;
                s_cory[t][k] = sn * lx + c * ly + cy;
            }

            // analytic argmin: 4x4 clamped window around the center contains
            // all fp-rounded tie candidates; lexicographic (d, idx) min with
            // reference-exact rn arithmetic == jnp.argmin first-occurrence.
            float wf = (cx + 51.2f) / 2.56f - 0.5f;
            float hf = (cy + 51.2f) / 2.56f - 0.5f;
            int w0 = min(max((int)floorf(wf) - 1, 0), WG - 4);
            int h0 = min(max((int)floorf(hf) - 1, 0), WG - 4);
            float bd = 3.0e38f;
            int   bg = 1 << 30;
#pragma unroll
            for (int dh = 0; dh < 4; dh++) {
#pragma unroll
                for (int dw = 0; dw < 4; dw++) {
                    int hi = h0 + dh, wi = w0 + dw;
                    float px = ((float)wi + 0.5f) / 40.0f * 102.4f - 51.2f;
                    float py = ((float)hi + 0.5f) / 40.0f * 102.4f - 51.2f;
                    float dx = __fsub_rn(px, cx), dy = __fsub_rn(py, cy);
                    float d = __fadd_rn(__fmul_rn(dx, dx), __fmul_rn(dy, dy));
                    if (d < bd) { bd = d; bg = hi * WG + wi; }
                }
            }
            s_gmin[t] = bg;
        }
        __syncthreads();

        const int cell = chunk * 256 + t;
        if (cell < GG) {
            const int wi = cell % WG, hi = cell / WG;
            const float px = ((float)wi + 0.5f) / 40.0f * 102.4f - 51.2f;
            const float py = ((float)hi + 0.5f) / 40.0f * 102.4f - 51.2f;

            unsigned long long m = 0ull;
#pragma unroll 4
            for (int i = 0; i < BPS; i++) {
                const float x0 = s_corx[i][0], y0 = s_cory[i][0];
                const float x1 = s_corx[i][1], y1 = s_cory[i][1];
                const float x2 = s_corx[i][2], y2 = s_cory[i][2];
                const float x3 = s_corx[i][3], y3 = s_cory[i][3];
                const float e0x = x1 - x0, e0y = y1 - y0;
                const float e1x = x2 - x1, e1y = y2 - y1;
                const float e2x = x3 - x2, e2y = y3 - y2;
                const float e3x = x0 - x3, e3y = y0 - y3;
                float c0 = e0x * (py - y0) - e0y * (px - x0);
                float c1 = e1x * (py - y1) - e1y * (px - x1);
                float c2 = e2x * (py - y2) - e2y * (px - x2);
                float c3 = e3x * (py - y3) - e3y * (px - x3);
                bool allpos = (c0 >= 0.0f) & (c1 >= 0.0f) & (c2 >= 0.0f) & (c3 >= 0.0f);
                bool allneg = (c0 <= 0.0f) & (c1 <= 0.0f) & (c2 <= 0.0f) & (c3 <= 0.0f);
                bool ins = (allpos | allneg) | (s_gmin[i] == cell);
                if (ins) m |= (1ull << (slice * BPS + i));
            }
            g_pmask[slice][b * GG + cell] = m;
        }
    }
}

// 112 blocks, launched with PDL (programmatic stream serialization): the
// prelude + launch latency overlap the var kernel; griddepcontrol.wait fires
// at primary completion WITH memory visibility (primary never triggers
// early), so the launch-boundary ordering argument is unchanged.
__global__ void __launch_bounds__(256) gather_kernel(float* __restrict__ out) {
    const int t = threadIdx.x;
    const int b     = blockIdx.x / 7;
    const int chunk = blockIdx.x % 7;
    const int cell  = chunk * 256 + t;
    const int row   = b * GG + cell;

    // wait for var_mask_kernel to fully complete (and its stores to land)
    asm volatile("griddepcontrol.wait;" ::: "memory");

    if (cell < GG) {
        unsigned long long m = __ldcg(&g_pmask[0][row]) | __ldcg(&g_pmask[1][row])
                             | __ldcg(&g_pmask[2][row]) | __ldcg(&g_pmask[3][row]);
        // flag = parity(mask)? msb(mask) : -1 (the reference scan's all_free
        // coupling is dead: each covering box simply toggles the cell)
        if (__popcll(m) & 1) {
            int f = 63 - __clzll(m);
            atomicAdd(&g_sums[b * MM + f], __ldcg(&g_var[row]));
            atomicAdd(&g_cnt[b * MM + f], 1);
        }
    }

    __threadfence();
    __syncthreads();
    __shared__ int s_tk;
    if (t == 0) s_tk = atomicAdd(&g_done, 1);
    __syncthreads();
    if (s_tk == NGATHER - 1) {
        __threadfence();
        float loss = 0.0f;
        int   pos  = 0;
#pragma unroll
        for (int k = 0; k < 4; k++) {
            int j = t + k * 256;
            int   c  = __ldcg(&g_cnt[j]);
            float sm = __ldcg(&g_sums[j]);
            if (c > 0) { loss += sm / (float)c; pos++; }
        }
#pragma unroll
        for (int o = 16; o > 0; o >>= 1) {
            loss += __shfl_xor_sync(0xFFFFFFFFu, loss, o);
            pos  += __shfl_xor_sync(0xFFFFFFFFu, pos,  o);
        }
        __shared__ float shl[8];
        __shared__ int   shp[8];
        if ((t & 31) == 0) { shl[t >> 5] = loss; shp[t >> 5] = pos; }
        __syncthreads();
        if (t == 0) {
            float L = 0.0f; int P = 0;
#pragma unroll
            for (int i = 0; i < 8; i++) { L += shl[i]; P += shp[i]; }
            if (P < 1) P = 1;
            out[0] = -L / (float)P;
        }
    }
}

extern "C" void kernel_launch(void* const* d_in, const int* in_sizes, int n_in,
                              void* d_out, int out_size) {
    const float* atten = (const float*)d_in[0];   // (16, 1600, 2048) fp32
    const float* bbox  = (const float*)d_in[1];   // (16, 64, 7) fp32
    float* out = (float*)d_out;

    var_mask_kernel<<<NBLK_VAR, 256>>>(atten, bbox);

    // PDL launch of the gather: overlaps its launch/prelude with the primary.
    cudaLaunchConfig_t cfg = {};
    cfg.gridDim  = dim3(NGATHER, 1, 1);
    cfg.blockDim = dim3(256, 1, 1);
    cfg.dynamicSmemBytes = 0;
    cfg.stream = 0;   // same (capture) stream as the <<<>>> launch above
    cudaLaunchAttribute attr[1];
    attr[0].id = cudaLaunchAttributeProgrammaticStreamSerialization;
    attr[0].val.programmaticStreamSerializationAllowed = 1;
    cfg.attrs = attr;
    cfg.numAttrs = 1;
    cudaLaunchKernelEx(&cfg, gather_kernel, out);
}

// round 17
// speedup vs baseline: 1.1183x; 1.0175x over previous
#include <cuda_runtime.h>
#include <math.h>

#define BB 16
#define GG 1600
#define DD 2048
#define MM 64
#define WG 40
#define NS 4              // box slices
#define BPS (MM / NS)     // 16 boxes per slice
#define NMASKBLK (BB * 7 * NS)   // 448 mask-carrying blocks
#define NGATHER (BB * 7)         // 112 gather blocks
#define NBLK_VAR (BB * GG / 8)   // 3200 blocks, warp-per-row

// ---- device-global scratch (no allocations allowed) ----
__device__ float g_var[BB * GG];
__device__ unsigned long long g_pmask[NS][BB * GG];  // partial inside|argmin masks
__device__ float g_sums[BB * MM];
__device__ int   g_cnt[BB * MM];

// Fused kernel: WARP-per-row variance (MLP=16, no block barrier, no fences/
// atomics anywhere in the streaming path — settled result of R4-R15: ANY
// sync machinery in this kernel costs ~10-12us) + mask slices on blocks
// 0..447 + accumulator zero-init on blocks 0..7.
__global__ void __launch_bounds__(256) var_mask_kernel(const float* __restrict__ atten,
                                                       const float* __restrict__ bboxes) {
    const int t = threadIdx.x;
    if (blockIdx.x < 8) {
        int gid = blockIdx.x * 256 + t;          // 2048 slots = 1024 + 1024
        if (gid < BB * MM) g_sums[gid] = 0.0f;
        else g_cnt[gid - BB * MM] = 0;
    }

    // ---- variance: one warp per (b,g) row ----
    const int row  = blockIdx.x * 8 + (t >> 5);
    const int lane = t & 31;
    const float4* p = reinterpret_cast<const float4*>(atten) + (size_t)row * (DD / 4);

    // shift by 0.5 (inputs U[0,1]) to kill cancellation in sumsq - sum^2/n;
    // two accumulator pairs to halve the serial FADD/FFMA chains.
    float sa = 0.0f, sb = 0.0f, qa = 0.0f, qb = 0.0f;
#pragma unroll
    for (int j = 0; j < 16; j++) {
        float4 v = __ldcs(p + lane + 32 * j);
        float a0 = v.x - 0.5f, a1 = v.y - 0.5f, a2 = v.z - 0.5f, a3 = v.w - 0.5f;
        sa += a0; sb += a1; sa += a2; sb += a3;
        qa = fmaf(a0, a0, qa); qb = fmaf(a1, a1, qb);
        qa = fmaf(a2, a2, qa); qb = fmaf(a3, a3, qb);
    }
    float s = sa + sb, s2 = qa + qb;
#pragma unroll
    for (int o = 16; o > 0; o >>= 1) {
        s  += __shfl_xor_sync(0xFFFFFFFFu, s,  o);
        s2 += __shfl_xor_sync(0xFFFFFFFFu, s2, o);
    }
    if (lane == 0)
        g_var[row] = (s2 - s * s / (float)DD) / (float)(DD - 1);

    // ---- mask slice on the first 448 blocks ----
    if (blockIdx.x < NMASKBLK) {
        const int slice = blockIdx.x & (NS - 1);
        const int bc    = blockIdx.x >> 2;       // b*7 + chunk
        const int b     = bc / 7;
        const int chunk = bc % 7;

        __shared__ float s_corx[BPS][4], s_cory[BPS][4];
        __shared__ int   s_gmin[BPS];

        if (t < BPS) {
            const int box = slice * BPS + t;
            const float* bbp = bboxes + ((size_t)b * MM + box) * 7;
            float cx = bbp[0], cy = bbp[1];
            float l = bbp[3], w = bbp[4];
            float ang = bbp[6];
            float rl = fminf(fmaxf(2.56f / l, 1.0f), 6.0f);
            float rw = fminf(fmaxf(2.56f / w, 1.0f), 6.0f);
            float el = l * rl, ew = w * rw;
            float c = cosf(ang), sn = sinf(ang);
            const float cnx[4] = {-0.5f, -0.5f, 0.5f, 0.5f};
            const float cny[4] = {-0.5f,  0.5f, 0.5f, -0.5f};
#pragma unroll
            for (int k = 0; k < 4; k++) {
                float lx = cnx[k] * el, ly = cny[k] * ew;
                s_corx[t][k] = c * lx - sn * ly + cx;
                s_cory[t][k] = sn * lx + c * ly + cy;
            }

            // analytic argmin: 4x4 clamped window around the center contains
            // all fp-rounded tie candidates; lexicographic (d, idx) min with
            // reference-exact rn arithmetic == jnp.argmin first-occurrence.
            float wf = (cx + 51.2f) / 2.56f - 0.5f;
            float hf = (cy + 51.2f) / 2.56f - 0.5f;
            int w0 = min(max((int)floorf(wf) - 1, 0), WG - 4);
            int h0 = min(max((int)floorf(hf) - 1, 0), WG - 4);
            float bd = 3.0e38f;
            int   bg = 1 << 30;
#pragma unroll
            for (int dh = 0; dh < 4; dh++) {
#pragma unroll
                for (int dw = 0; dw < 4; dw++) {
                    int hi = h0 + dh, wi = w0 + dw;
                    float px = ((float)wi + 0.5f) / 40.0f * 102.4f - 51.2f;
                    float py = ((float)hi + 0.5f) / 40.0f * 102.4f - 51.2f;
                    float dx = __fsub_rn(px, cx), dy = __fsub_rn(py, cy);
                    float d = __fadd_rn(__fmul_rn(dx, dx), __fmul_rn(dy, dy));
                    if (d < bd) { bd = d; bg = hi * WG + wi; }
                }
            }
            s_gmin[t] = bg;
        }
        __syncthreads();

        const int cell = chunk * 256 + t;
        if (cell < GG) {
            const int wi = cell % WG, hi = cell / WG;
            const float px = ((float)wi + 0.5f) / 40.0f * 102.4f - 51.2f;
            const float py = ((float)hi + 0.5f) / 40.0f * 102.4f - 51.2f;

            unsigned long long m = 0ull;
#pragma unroll 4
            for (int i = 0; i < BPS; i++) {
                const float x0 = s_corx[i][0], y0 = s_cory[i][0];
                const float x1 = s_corx[i][1], y1 = s_cory[i][1];
                const float x2 = s_corx[i][2], y2 = s_cory[i][2];
                const float x3 = s_corx[i][3], y3 = s_cory[i][3];
                const float e0x = x1 - x0, e0y = y1 - y0;
                const float e1x = x2 - x1, e1y = y2 - y1;
                const float e2x = x3 - x2, e2y = y3 - y2;
                const float e3x = x0 - x3, e3y = y0 - y3;
                float c0 = e0x * (py - y0) - e0y * (px - x0);
                float c1 = e1x * (py - y1) - e1y * (px - x1);
                float c2 = e2x * (py - y2) - e2y * (px - x2);
                float c3 = e3x * (py - y3) - e3y * (px - x3);
                bool allpos = (c0 >= 0.0f) & (c1 >= 0.0f) & (c2 >= 0.0f) & (c3 >= 0.0f);
                bool allneg = (c0 <= 0.0f) & (c1 <= 0.0f) & (c2 <= 0.0f) & (c3 <= 0.0f);
                bool ins = (allpos | allneg) | (s_gmin[i] == cell);
                if (ins) m |= (1ull << (slice * BPS + i));
            }
            g_pmask[slice][b * GG + cell] = m;
        }
    }
}

// 112 blocks, PDL secondary: wait for var_mask completion (full memory
// visibility), then one cell per thread: OR the 4 pmask slices, derive
// flag = parity(mask)? msb(mask) : -1 (the reference scan's all_free
// coupling is dead: each covering box simply toggles the cell), 2 scattered
// L2 atomics, exit. No fence, no ticket — the next PDL boundary orders it.
__global__ void __launch_bounds__(256) gather_kernel() {
    const int t = threadIdx.x;
    const int b     = blockIdx.x / 7;
    const int chunk = blockIdx.x % 7;
    const int cell  = chunk * 256 + t;
    const int row   = b * GG + cell;

    asm volatile("griddepcontrol.wait;" ::: "memory");

    if (cell < GG) {
        unsigned long long m = __ldcg(&g_pmask[0][row]) | __ldcg(&g_pmask[1][row])
                             | __ldcg(&g_pmask[2][row]) | __ldcg(&g_pmask[3][row]);
        if (__popcll(m) & 1) {
            int f = 63 - __clzll(m);
            atomicAdd(&g_sums[b * MM + f], __ldcg(&g_var[row]));
            atomicAdd(&g_cnt[b * MM + f], 1);
        }
    }
}

// 1 block, PDL tertiary: wait for gather completion, reduce the 1024
// (batch,box) accumulators into the loss.
__global__ void __launch_bounds__(256) finalize_kernel(float* __restrict__ out) {
    const int t = threadIdx.x;
    asm volatile("griddepcontrol.wait;" ::: "memory");

    float loss = 0.0f;
    int   pos  = 0;
#pragma unroll
    for (int k = 0; k < 4; k++) {
        int j = t + k * 256;
        int   c  = __ldcg(&g_cnt[j]);
        float sm = __ldcg(&g_sums[j]);
        if (c > 0) { loss += sm / (float)c; pos++; }
    }
#pragma unroll
    for (int o = 16; o > 0; o >>= 1) {
        loss += __shfl_xor_sync(0xFFFFFFFFu, loss, o);
        pos  += __shfl_xor_sync(0xFFFFFFFFu, pos,  o);
    }
    __shared__ float shl[8];
    __shared__ int   shp[8];
    if ((t & 31) == 0) { shl[t >> 5] = loss; shp[t >> 5] = pos; }
    __syncthreads();
    if (t == 0) {
        float L = 0.0f; int P = 0;
#pragma unroll
        for (int i = 0; i < 8; i++) { L += shl[i]; P += shp[i]; }
        if (P < 1) P = 1;
        out[0] = -L / (float)P;
    }
}

extern "C" void kernel_launch(void* const* d_in, const int* in_sizes, int n_in,
                              void* d_out, int out_size) {
    const float* atten = (const float*)d_in[0];   // (16, 1600, 2048) fp32
    const float* bbox  = (const float*)d_in[1];   // (16, 64, 7) fp32
    float* out = (float*)d_out;

    var_mask_kernel<<<NBLK_VAR, 256>>>(atten, bbox);

    cudaLaunchAttribute attr[1];
    attr[0].id = cudaLaunchAttributeProgrammaticStreamSerialization;
    attr[0].val.programmaticStreamSerializationAllowed = 1;

    cudaLaunchConfig_t cfg1 = {};
    cfg1.gridDim  = dim3(NGATHER, 1, 1);
    cfg1.blockDim = dim3(256, 1, 1);
    cfg1.stream = 0;
    cfg1.attrs = attr;
    cfg1.numAttrs = 1;
    cudaLaunchKernelEx(&cfg1, gather_kernel);

    cudaLaunchConfig_t cfg2 = {};
    cfg2.gridDim  = dim3(1, 1, 1);
    cfg2.blockDim = dim3(256, 1, 1);
    cfg2.stream = 0;
    cfg2.attrs = attr;
    cfg2.numAttrs = 1;
    cudaLaunchKernelEx(&cfg2, finalize_kernel, out);
}